// round 1
// baseline (speedup 1.0000x reference)
#include <cuda_runtime.h>
#include <cuda_bf16.h>
#include <math.h>

// Shapes (fixed by problem)
#define NB   16
#define CC   64
#define FF   8
#define HWSZ 3136          // 56*56
#define ROWS (NB*CC*FF)    // 8192
#define ITER 128
#define OUTC 256
#define EMB  20
#define EPSV 1e-5f

// Scratch (__device__ globals; no allocation allowed)
// acc layout: [0:64) bn0 sum, [64:128) bn0 sq, [128:256) bn1 sum,
//             [256:384) bn1 sq, [384:640) bn2 sum, [640:896) bn2 sq
__device__ float g_acc[896];
__device__ float g_top5[ROWS * 5];
__device__ float g_si[NB * CC * 7 * 20];     // 143360
__device__ float g_y1[NB * ITER * 7 * 10];   // 143360
__device__ float g_y2[NB * OUTC * 7 * 5];    // 143360

__global__ void k_zero() {
    if (threadIdx.x < 896) g_acc[threadIdx.x] = 0.f;
}

// ---------------------------------------------------------------------------
// K1: one block per (n,c,f) row (8192 blocks). Streams 3136 floats,
// accumulates per-channel sum/sumsq (atomics) and raw top-5 (block tree merge).
// ---------------------------------------------------------------------------
__global__ void __launch_bounds__(256) k1_stats_top5(const float* __restrict__ h) {
    const int row = blockIdx.x;
    const int c = (row / FF) % CC;
    const float4* p = reinterpret_cast<const float4*>(h + (size_t)row * HWSZ);

    float t0 = -1e30f, t1 = -1e30f, t2 = -1e30f, t3 = -1e30f, t4 = -1e30f;
    float s = 0.f, sq = 0.f;

    for (int i = threadIdx.x; i < HWSZ / 4; i += 256) {
        float4 v4 = p[i];
        #pragma unroll
        for (int j = 0; j < 4; j++) {
            float v = (&v4.x)[j];
            s += v; sq += v * v;
            if (v > t4) {
                if (v > t2) {
                    if (v > t0)      { t4 = t3; t3 = t2; t2 = t1; t1 = t0; t0 = v; }
                    else if (v > t1) { t4 = t3; t3 = t2; t2 = t1; t1 = v; }
                    else             { t4 = t3; t3 = t2; t2 = v; }
                } else {
                    if (v > t3)      { t4 = t3; t3 = v; }
                    else             { t4 = v; }
                }
            }
        }
    }

    // sum/sumsq block reduction -> atomics
    __shared__ float s_red[16];
    #pragma unroll
    for (int o = 16; o; o >>= 1) {
        s  += __shfl_down_sync(0xffffffffu, s,  o);
        sq += __shfl_down_sync(0xffffffffu, sq, o);
    }
    const int lane = threadIdx.x & 31, wid = threadIdx.x >> 5;
    if (lane == 0) { s_red[wid] = s; s_red[8 + wid] = sq; }

    // top-5 block tree merge
    __shared__ float stp[256 * 5];
    float* mine = &stp[threadIdx.x * 5];
    mine[0] = t0; mine[1] = t1; mine[2] = t2; mine[3] = t3; mine[4] = t4;
    __syncthreads();

    if (threadIdx.x == 0) {
        float S = 0.f, Q = 0.f;
        #pragma unroll
        for (int w = 0; w < 8; w++) { S += s_red[w]; Q += s_red[8 + w]; }
        atomicAdd(&g_acc[c], S);
        atomicAdd(&g_acc[64 + c], Q);
    }

    for (int str = 128; str > 0; str >>= 1) {
        if (threadIdx.x < str) {
            float a[5], b[5];
            #pragma unroll
            for (int k = 0; k < 5; k++) { a[k] = mine[k]; b[k] = stp[(threadIdx.x + str) * 5 + k]; }
            int ia = 0, ib = 0;
            #pragma unroll
            for (int k = 0; k < 5; k++) mine[k] = (a[ia] >= b[ib]) ? a[ia++] : b[ib++];
        }
        __syncthreads();
    }
    if (threadIdx.x < 5) g_top5[row * 5 + threadIdx.x] = stp[threadIdx.x];
}

// ---------------------------------------------------------------------------
// K3: one block per (n,c) (1024 blocks). Full attention chain in shared mem.
// BN0 finalization fused (scale/shift computed from accumulators).
// ---------------------------------------------------------------------------
__global__ void __launch_bounds__(256) k3_attn(
    const float* __restrict__ bn0_g, const float* __restrict__ bn0_b,
    const float* __restrict__ up_w,  const float* __restrict__ up_b,
    const float* __restrict__ up2_w, const float* __restrict__ up2_b,
    const float* __restrict__ up3_w, const float* __restrict__ up3_b,
    const float* __restrict__ wW,    const float* __restrict__ wproj,
    const float* __restrict__ wW2,   const float* __restrict__ wproj2)
{
    const int b = blockIdx.x;          // n*64 + c
    const int c = b & 63;
    const int tid = threadIdx.x;

    __shared__ float s5[8][5], st[8][25], su[8][25], spa[8][5], ssc[8][25];
    __shared__ float scen[8][2], sc20[7][20], su2[7][20], satt2[8], sbn[2];

    if (tid == 0) {
        const float inv = 1.f / 401408.f;   // N*F*H*W
        float m = g_acc[c] * inv;
        float v = g_acc[64 + c] * inv - m * m;
        float sc = bn0_g[c] * rsqrtf(v + EPSV);
        sbn[0] = sc; sbn[1] = bn0_b[c] - m * sc;
    }
    __syncthreads();

    if (tid < 40) {
        s5[tid / 5][tid % 5] = g_top5[b * 40 + tid] * sbn[0] + sbn[1];
    }
    __syncthreads();

    if (tid < 200) {                    // t = top5 @ up2_w.T + up2_b
        int f = tid / 25, j = tid % 25;
        float a = up2_b[j];
        #pragma unroll
        for (int k = 0; k < 5; k++) a += s5[f][k] * up2_w[j * 5 + k];
        st[f][j] = a;
    }
    __syncthreads();

    if (tid < 200) {                    // u = tanh(t @ wW)
        int f = tid / 25, j = tid % 25;
        float a = 0.f;
        #pragma unroll
        for (int k = 0; k < 25; k++) a += st[f][k] * wW[k * 25 + j];
        su[f][j] = tanhf(a);
    }
    __syncthreads();

    if (tid < 8) {                      // att = softmax(u@wproj); t3; pa = t3*att
        int f = tid;
        float lg[5], t3v[5];
        #pragma unroll
        for (int a2 = 0; a2 < 5; a2++) {
            float l = 0.f, t3 = up3_b[a2];
            #pragma unroll
            for (int k = 0; k < 25; k++) {
                l  += su[f][k] * wproj[k * 5 + a2];
                t3 += st[f][k] * up3_w[a2 * 25 + k];
            }
            lg[a2] = l; t3v[a2] = t3;
        }
        float mx = lg[0];
        #pragma unroll
        for (int a2 = 1; a2 < 5; a2++) mx = fmaxf(mx, lg[a2]);
        float sum = 0.f;
        #pragma unroll
        for (int a2 = 0; a2 < 5; a2++) { lg[a2] = __expf(lg[a2] - mx); sum += lg[a2]; }
        float r = 1.f / sum;
        #pragma unroll
        for (int a2 = 0; a2 < 5; a2++) spa[f][a2] = t3v[a2] * lg[a2] * r;
    }
    __syncthreads();

    if (tid < 200) {                    // scored = pa @ up2_w.T + up2_b
        int f = tid / 25, j = tid % 25;
        float a = up2_b[j];
        #pragma unroll
        for (int k = 0; k < 5; k++) a += spa[f][k] * up2_w[j * 5 + k];
        ssc[f][j] = a;
    }
    __syncthreads();

    if (tid < 16) {                     // cen = scored @ coords
        int f = tid >> 1, d = tid & 1;
        float a = 0.f;
        #pragma unroll
        for (int j = 0; j < 25; j++) {
            float cd = d ? (float)(j % 5) : (float)(j / 5);
            a += ssc[f][j] * cd;
        }
        scen[f][d] = a;
    }
    __syncthreads();

    if (tid < 140) {                    // frame diff, then @ up_w.T + up_b
        int fr = tid / 20, k = tid % 20;
        float d0 = scen[fr + 1][0] - scen[fr][0];
        float d1 = scen[fr + 1][1] - scen[fr][1];
        sc20[fr][k] = d0 * up_w[k * 2] + d1 * up_w[k * 2 + 1] + up_b[k];
    }
    __syncthreads();

    if (tid < 140) {                    // u2 = tanh(wW2 @ cen)
        int fr = tid / 20, k = tid % 20;
        float a = 0.f;
        #pragma unroll
        for (int j = 0; j < 7; j++) a += wW2[fr * 7 + j] * sc20[j][k];
        su2[fr][k] = tanhf(a);
    }
    __syncthreads();

    if (tid < 7) {                      // logits over frames
        float a = 0.f;
        #pragma unroll
        for (int k = 0; k < 20; k++) a += su2[tid][k] * wproj2[k];
        satt2[tid] = a;
    }
    __syncthreads();
    if (tid == 0) {                     // softmax over 7 frames
        float mx = satt2[0];
        #pragma unroll
        for (int j = 1; j < 7; j++) mx = fmaxf(mx, satt2[j]);
        float sum = 0.f;
        #pragma unroll
        for (int j = 0; j < 7; j++) { satt2[j] = __expf(satt2[j] - mx); sum += satt2[j]; }
        float r = 1.f / sum;
        #pragma unroll
        for (int j = 0; j < 7; j++) satt2[j] *= r;
    }
    __syncthreads();

    if (tid < 140) {                    // si = cen * att2
        int fr = tid / 20, k = tid % 20;
        g_si[(b * 7 + fr) * 20 + k] = sc20[fr][k] * satt2[fr];
    }
}

// ---------------------------------------------------------------------------
// K4: conv1 (128,64,1,3) stride (1,2) pad (0,1) + bn1 stats.
// Block per (n,fr) = 112 blocks. Weights staged through shared in ic-tiles.
// ---------------------------------------------------------------------------
__global__ void __launch_bounds__(256) k4_conv1(const float* __restrict__ w1) {
    const int nb = blockIdx.x, n = nb / 7, fr = nb % 7;
    const int tid = threadIdx.x;
    __shared__ float s_in[64][21];        // zero-padded left column
    __shared__ float s_w[128][25];        // ic-tile of 8 -> 24 used (+pad)

    for (int i = tid; i < 64 * 20; i += 256) {
        int ic = i / 20, w = i % 20;
        s_in[ic][w + 1] = g_si[((n * 64 + ic) * 7 + fr) * 20 + w];
    }
    if (tid < 64) s_in[tid][0] = 0.f;

    float acc[5] = {0, 0, 0, 0, 0};
    const int oc = tid & 127, half = tid >> 7;

    for (int ict = 0; ict < 64; ict += 8) {
        __syncthreads();
        for (int i = tid; i < 128 * 24; i += 256)
            s_w[i / 24][i % 24] = w1[(i / 24) * 192 + ict * 3 + (i % 24)];
        __syncthreads();
        #pragma unroll
        for (int ii = 0; ii < 8; ii++) {
            int ic = ict + ii;
            #pragma unroll
            for (int k = 0; k < 3; k++) {
                float wv = s_w[oc][ii * 3 + k];
                #pragma unroll
                for (int m = 0; m < 5; m++) {
                    int ow = half * 5 + m;
                    acc[m] += wv * s_in[ic][2 * ow + k];
                }
            }
        }
    }

    float ps = 0.f, psq = 0.f;
    #pragma unroll
    for (int m = 0; m < 5; m++) {
        int ow = half * 5 + m;
        g_y1[((n * 128 + oc) * 7 + fr) * 10 + ow] = acc[m];
        ps += acc[m]; psq += acc[m] * acc[m];
    }
    atomicAdd(&g_acc[128 + oc], ps);
    atomicAdd(&g_acc[256 + oc], psq);
}

// ---------------------------------------------------------------------------
// K6: tanh(bn1(y1)) inline, conv2 (256,128,1,3) stride (1,2) pad (0,1) + bn2 stats.
// Block per (n,fr) = 112 blocks. Weights staged through shared in ic-tiles.
// ---------------------------------------------------------------------------
__global__ void __launch_bounds__(256) k6_conv2(const float* __restrict__ w2,
                                                const float* __restrict__ bn1_g,
                                                const float* __restrict__ bn1_b) {
    const int nb = blockIdx.x, n = nb / 7, fr = nb % 7;
    const int tid = threadIdx.x;
    __shared__ float s_x[128][11];        // zero-padded left column
    __shared__ float s_w[256][25];        // ic-tile of 8 -> 24 used (+pad)
    __shared__ float s_sc[128], s_sh[128];

    if (tid < 128) {
        const float inv = 1.f / 1120.f;   // N*7*10
        float m = g_acc[128 + tid] * inv;
        float v = g_acc[256 + tid] * inv - m * m;
        float sc = bn1_g[tid] * rsqrtf(v + EPSV);
        s_sc[tid] = sc; s_sh[tid] = bn1_b[tid] - m * sc;
    }
    __syncthreads();
    for (int i = tid; i < 128 * 10; i += 256) {
        int ic = i / 10, w = i % 10;
        s_x[ic][w + 1] = tanhf(g_y1[((n * 128 + ic) * 7 + fr) * 10 + w] * s_sc[ic] + s_sh[ic]);
    }
    if (tid < 128) s_x[tid][0] = 0.f;

    float acc[5] = {0, 0, 0, 0, 0};
    const int oc = tid;

    for (int ict = 0; ict < 128; ict += 8) {
        __syncthreads();
        for (int i = tid; i < 256 * 24; i += 256)
            s_w[i / 24][i % 24] = w2[(i / 24) * 384 + ict * 3 + (i % 24)];
        __syncthreads();
        #pragma unroll
        for (int ii = 0; ii < 8; ii++) {
            int ic = ict + ii;
            #pragma unroll
            for (int k = 0; k < 3; k++) {
                float wv = s_w[oc][ii * 3 + k];
                #pragma unroll
                for (int m = 0; m < 5; m++) acc[m] += wv * s_x[ic][2 * m + k];
            }
        }
    }

    float ps = 0.f, psq = 0.f;
    #pragma unroll
    for (int m = 0; m < 5; m++) {
        g_y2[((n * 256 + oc) * 7 + fr) * 5 + m] = acc[m];
        ps += acc[m]; psq += acc[m] * acc[m];
    }
    atomicAdd(&g_acc[384 + oc], ps);
    atomicAdd(&g_acc[640 + oc], psq);
}

// ---------------------------------------------------------------------------
// K8: bn2 + tanh + mean over width (AvgPool (1,5)). 28672 outputs.
// ---------------------------------------------------------------------------
__global__ void __launch_bounds__(256) k8_final(const float* __restrict__ bn2_g,
                                                const float* __restrict__ bn2_b,
                                                float* __restrict__ out) {
    const int o = blockIdx.x * 256 + threadIdx.x;
    if (o >= NB * OUTC * 7) return;
    const int fr = o % 7;
    const int oc = (o / 7) % OUTC;
    const float inv = 1.f / 560.f;        // N*7*5
    float m = g_acc[384 + oc] * inv;
    float v = g_acc[640 + oc] * inv - m * m;
    float sc = bn2_g[oc] * rsqrtf(v + EPSV);
    float sh = bn2_b[oc] - m * sc;
    const float* y = &g_y2[o * 5];        // (n,oc,fr) contiguous * 5
    float a = 0.f;
    #pragma unroll
    for (int w = 0; w < 5; w++) a += tanhf(y[w] * sc + sh);
    out[o] = a * 0.2f;
}

// ---------------------------------------------------------------------------
extern "C" void kernel_launch(void* const* d_in, const int* in_sizes, int n_in,
                              void* d_out, int out_size) {
    const float* h      = (const float*)d_in[0];
    const float* bn0_g  = (const float*)d_in[1];
    const float* bn0_b  = (const float*)d_in[2];
    const float* up_w   = (const float*)d_in[3];
    const float* up_b   = (const float*)d_in[4];
    const float* up2_w  = (const float*)d_in[5];
    const float* up2_b  = (const float*)d_in[6];
    const float* up3_w  = (const float*)d_in[7];
    const float* up3_b  = (const float*)d_in[8];
    const float* wW     = (const float*)d_in[9];
    const float* wproj  = (const float*)d_in[10];
    const float* wW2    = (const float*)d_in[11];
    const float* wproj2 = (const float*)d_in[12];
    const float* conv1w = (const float*)d_in[13];
    const float* bn1_g  = (const float*)d_in[14];
    const float* bn1_b  = (const float*)d_in[15];
    const float* conv2w = (const float*)d_in[16];
    const float* bn2_g  = (const float*)d_in[17];
    const float* bn2_b  = (const float*)d_in[18];

    k_zero<<<1, 896>>>();
    k1_stats_top5<<<ROWS, 256>>>(h);
    k3_attn<<<NB * CC, 256>>>(bn0_g, bn0_b, up_w, up_b, up2_w, up2_b,
                              up3_w, up3_b, wW, wproj, wW2, wproj2);
    k4_conv1<<<NB * 7, 256>>>(conv1w);
    k6_conv2<<<NB * 7, 256>>>(conv2w, bn1_g, bn1_b);
    k8_final<<<(NB * OUTC * 7 + 255) / 256, 256>>>(bn2_g, bn2_b, (float*)d_out);
}

// round 13
// speedup vs baseline: 1.4032x; 1.4032x over previous
#include <cuda_runtime.h>
#include <cuda_bf16.h>
#include <math.h>

// Shapes (fixed by problem)
#define NB   16
#define CC   64
#define FF   8
#define HWSZ 3136          // 56*56
#define ROWS (NB*CC*FF)    // 8192
#define ITER 128
#define OUTC 256
#define EMB  20
#define EPSV 1e-5f

// Scratch (__device__ globals; no allocation allowed)
// acc layout: [0:64) bn0 sum, [64:128) bn0 sq, [128:256) bn1 sum,
//             [256:384) bn1 sq, [384:640) bn2 sum, [640:896) bn2 sq
__device__ float g_acc[896];
__device__ float g_top5[ROWS * 5];
__device__ float g_si[NB * CC * 7 * 20];     // 143360
__device__ float g_y1[NB * ITER * 7 * 10];   // 143360
__device__ float g_y2[NB * OUTC * 7 * 5];    // 143360

__global__ void k_zero() {
    if (threadIdx.x < 896) g_acc[threadIdx.x] = 0.f;
}

// ---------------------------------------------------------------------------
// K1: one block per (n,c,f) row (8192 blocks). Streams 3136 floats,
// accumulates per-channel sum/sumsq (atomics) and raw top-5 (block tree merge).
// Monotone-BN trick: top5(bn(x)) == bn(top5(x)) since bn scale > 0, so only
// raw top-5 + channel stats are needed from the 103 MB input (single pass).
// ---------------------------------------------------------------------------
__global__ void __launch_bounds__(256) k1_stats_top5(const float* __restrict__ h) {
    const int row = blockIdx.x;
    const int c = (row / FF) % CC;
    const float4* p = reinterpret_cast<const float4*>(h + (size_t)row * HWSZ);

    float t0 = -1e30f, t1 = -1e30f, t2 = -1e30f, t3 = -1e30f, t4 = -1e30f;
    float s = 0.f, sq = 0.f;

    for (int i = threadIdx.x; i < HWSZ / 4; i += 256) {
        float4 v4 = p[i];
        #pragma unroll
        for (int j = 0; j < 4; j++) {
            float v = (&v4.x)[j];
            s += v; sq += v * v;
            if (v > t4) {
                if (v > t2) {
                    if (v > t0)      { t4 = t3; t3 = t2; t2 = t1; t1 = t0; t0 = v; }
                    else if (v > t1) { t4 = t3; t3 = t2; t2 = t1; t1 = v; }
                    else             { t4 = t3; t3 = t2; t2 = v; }
                } else {
                    if (v > t3)      { t4 = t3; t3 = v; }
                    else             { t4 = v; }
                }
            }
        }
    }

    // sum/sumsq block reduction -> atomics
    __shared__ float s_red[16];
    #pragma unroll
    for (int o = 16; o; o >>= 1) {
        s  += __shfl_down_sync(0xffffffffu, s,  o);
        sq += __shfl_down_sync(0xffffffffu, sq, o);
    }
    const int lane = threadIdx.x & 31, wid = threadIdx.x >> 5;
    if (lane == 0) { s_red[wid] = s; s_red[8 + wid] = sq; }

    // top-5 block tree merge
    __shared__ float stp[256 * 5];
    float* mine = &stp[threadIdx.x * 5];
    mine[0] = t0; mine[1] = t1; mine[2] = t2; mine[3] = t3; mine[4] = t4;
    __syncthreads();

    if (threadIdx.x == 0) {
        float S = 0.f, Q = 0.f;
        #pragma unroll
        for (int w = 0; w < 8; w++) { S += s_red[w]; Q += s_red[8 + w]; }
        atomicAdd(&g_acc[c], S);
        atomicAdd(&g_acc[64 + c], Q);
    }

    for (int str = 128; str > 0; str >>= 1) {
        if (threadIdx.x < str) {
            float a[5], b[5];
            #pragma unroll
            for (int k = 0; k < 5; k++) { a[k] = mine[k]; b[k] = stp[(threadIdx.x + str) * 5 + k]; }
            int ia = 0, ib = 0;
            #pragma unroll
            for (int k = 0; k < 5; k++) mine[k] = (a[ia] >= b[ib]) ? a[ia++] : b[ib++];
        }
        __syncthreads();
    }
    if (threadIdx.x < 5) g_top5[row * 5 + threadIdx.x] = stp[threadIdx.x];
}

// ---------------------------------------------------------------------------
// K3: one block per (n,c) (1024 blocks). Full attention chain in shared mem.
// BN0 finalization fused (scale/shift computed from accumulators).
// ---------------------------------------------------------------------------
__global__ void __launch_bounds__(256) k3_attn(
    const float* __restrict__ bn0_g, const float* __restrict__ bn0_b,
    const float* __restrict__ up_w,  const float* __restrict__ up_b,
    const float* __restrict__ up2_w, const float* __restrict__ up2_b,
    const float* __restrict__ up3_w, const float* __restrict__ up3_b,
    const float* __restrict__ wW,    const float* __restrict__ wproj,
    const float* __restrict__ wW2,   const float* __restrict__ wproj2)
{
    const int b = blockIdx.x;          // n*64 + c
    const int c = b & 63;
    const int tid = threadIdx.x;

    __shared__ float s5[8][5], st[8][25], su[8][25], spa[8][5], ssc[8][25];
    __shared__ float scen[8][2], sc20[7][20], su2[7][20], satt2[8], sbn[2];

    if (tid == 0) {
        const float inv = 1.f / 401408.f;   // N*F*H*W
        float m = g_acc[c] * inv;
        float v = g_acc[64 + c] * inv - m * m;
        float sc = bn0_g[c] * rsqrtf(v + EPSV);
        sbn[0] = sc; sbn[1] = bn0_b[c] - m * sc;
    }
    __syncthreads();

    if (tid < 40) {
        s5[tid / 5][tid % 5] = g_top5[b * 40 + tid] * sbn[0] + sbn[1];
    }
    __syncthreads();

    if (tid < 200) {                    // t = top5 @ up2_w.T + up2_b
        int f = tid / 25, j = tid % 25;
        float a = up2_b[j];
        #pragma unroll
        for (int k = 0; k < 5; k++) a += s5[f][k] * up2_w[j * 5 + k];
        st[f][j] = a;
    }
    __syncthreads();

    if (tid < 200) {                    // u = tanh(t @ wW)
        int f = tid / 25, j = tid % 25;
        float a = 0.f;
        #pragma unroll
        for (int k = 0; k < 25; k++) a += st[f][k] * wW[k * 25 + j];
        su[f][j] = tanhf(a);
    }
    __syncthreads();

    if (tid < 8) {                      // att = softmax(u@wproj); t3; pa = t3*att
        int f = tid;
        float lg[5], t3v[5];
        #pragma unroll
        for (int a2 = 0; a2 < 5; a2++) {
            float l = 0.f, t3 = up3_b[a2];
            #pragma unroll
            for (int k = 0; k < 25; k++) {
                l  += su[f][k] * wproj[k * 5 + a2];
                t3 += st[f][k] * up3_w[a2 * 25 + k];
            }
            lg[a2] = l; t3v[a2] = t3;
        }
        float mx = lg[0];
        #pragma unroll
        for (int a2 = 1; a2 < 5; a2++) mx = fmaxf(mx, lg[a2]);
        float sum = 0.f;
        #pragma unroll
        for (int a2 = 0; a2 < 5; a2++) { lg[a2] = __expf(lg[a2] - mx); sum += lg[a2]; }
        float r = 1.f / sum;
        #pragma unroll
        for (int a2 = 0; a2 < 5; a2++) spa[f][a2] = t3v[a2] * lg[a2] * r;
    }
    __syncthreads();

    if (tid < 200) {                    // scored = pa @ up2_w.T + up2_b
        int f = tid / 25, j = tid % 25;
        float a = up2_b[j];
        #pragma unroll
        for (int k = 0; k < 5; k++) a += spa[f][k] * up2_w[j * 5 + k];
        ssc[f][j] = a;
    }
    __syncthreads();

    if (tid < 16) {                     // cen = scored @ coords
        int f = tid >> 1, d = tid & 1;
        float a = 0.f;
        #pragma unroll
        for (int j = 0; j < 25; j++) {
            float cd = d ? (float)(j % 5) : (float)(j / 5);
            a += ssc[f][j] * cd;
        }
        scen[f][d] = a;
    }
    __syncthreads();

    if (tid < 140) {                    // frame diff, then @ up_w.T + up_b
        int fr = tid / 20, k = tid % 20;
        float d0 = scen[fr + 1][0] - scen[fr][0];
        float d1 = scen[fr + 1][1] - scen[fr][1];
        sc20[fr][k] = d0 * up_w[k * 2] + d1 * up_w[k * 2 + 1] + up_b[k];
    }
    __syncthreads();

    if (tid < 140) {                    // u2 = tanh(wW2 @ cen)
        int fr = tid / 20, k = tid % 20;
        float a = 0.f;
        #pragma unroll
        for (int j = 0; j < 7; j++) a += wW2[fr * 7 + j] * sc20[j][k];
        su2[fr][k] = tanhf(a);
    }
    __syncthreads();

    if (tid < 7) {                      // logits over frames
        float a = 0.f;
        #pragma unroll
        for (int k = 0; k < 20; k++) a += su2[tid][k] * wproj2[k];
        satt2[tid] = a;
    }
    __syncthreads();
    if (tid == 0) {                     // softmax over 7 frames
        float mx = satt2[0];
        #pragma unroll
        for (int j = 1; j < 7; j++) mx = fmaxf(mx, satt2[j]);
        float sum = 0.f;
        #pragma unroll
        for (int j = 0; j < 7; j++) { satt2[j] = __expf(satt2[j] - mx); sum += satt2[j]; }
        float r = 1.f / sum;
        #pragma unroll
        for (int j = 0; j < 7; j++) satt2[j] *= r;
    }
    __syncthreads();

    if (tid < 140) {                    // si = cen * att2
        int fr = tid / 20, k = tid % 20;
        g_si[(b * 7 + fr) * 20 + k] = sc20[fr][k] * satt2[fr];
    }
}

// ---------------------------------------------------------------------------
// K4: conv1 (128,64,1,3) stride (1,2) pad (0,1) + bn1 stats.
// Block per (n,fr) = 112 blocks. Direct vectorized weight loads (no staging,
// no barriers in mainloop): each thread streams its oc's 192-float weight row
// as float4s (perfect intra-thread locality, L1-cached).
// ---------------------------------------------------------------------------
__global__ void __launch_bounds__(256) k4_conv1(const float* __restrict__ w1) {
    const int nb = blockIdx.x, n = nb / 7, fr = nb % 7;
    const int tid = threadIdx.x;
    __shared__ float s_in[64][22];        // zero-padded left column, +pad

    for (int i = tid; i < 64 * 20; i += 256) {
        int ic = i / 20, w = i % 20;
        s_in[ic][w + 1] = g_si[((n * 64 + ic) * 7 + fr) * 20 + w];
    }
    if (tid < 64) s_in[tid][0] = 0.f;
    __syncthreads();

    const int oc = tid & 127, half = tid >> 7;
    const float4* wr = reinterpret_cast<const float4*>(w1 + oc * 192);
    const int ow0 = half * 5;
    float acc[5] = {0, 0, 0, 0, 0};

    #pragma unroll 4
    for (int icg = 0; icg < 16; icg++) {   // 4 ic per group, 3 float4 of weights
        float4 wa = wr[icg * 3 + 0];
        float4 wb = wr[icg * 3 + 1];
        float4 wc = wr[icg * 3 + 2];
        float wv[12] = {wa.x, wa.y, wa.z, wa.w, wb.x, wb.y, wb.z, wb.w,
                        wc.x, wc.y, wc.z, wc.w};
        const int ic0 = icg * 4;
        #pragma unroll
        for (int ii = 0; ii < 4; ii++) {
            #pragma unroll
            for (int k = 0; k < 3; k++) {
                float wf = wv[ii * 3 + k];
                #pragma unroll
                for (int m = 0; m < 5; m++)
                    acc[m] += wf * s_in[ic0 + ii][2 * (ow0 + m) + k];
            }
        }
    }

    float ps = 0.f, psq = 0.f;
    #pragma unroll
    for (int m = 0; m < 5; m++) {
        g_y1[((n * 128 + oc) * 7 + fr) * 10 + ow0 + m] = acc[m];
        ps += acc[m]; psq += acc[m] * acc[m];
    }
    atomicAdd(&g_acc[128 + oc], ps);
    atomicAdd(&g_acc[256 + oc], psq);
}

// ---------------------------------------------------------------------------
// K6: tanh(bn1(y1)) inline, conv2 (256,128,1,3) stride (1,2) pad (0,1) + bn2
// stats. Block per (n,fr) = 112 blocks, thread per oc. Direct vectorized
// weight loads (384-float row per thread as float4s).
// ---------------------------------------------------------------------------
__global__ void __launch_bounds__(256) k6_conv2(const float* __restrict__ w2,
                                                const float* __restrict__ bn1_g,
                                                const float* __restrict__ bn1_b) {
    const int nb = blockIdx.x, n = nb / 7, fr = nb % 7;
    const int tid = threadIdx.x;
    __shared__ float s_x[128][12];        // zero-padded left column, +pad
    __shared__ float s_sc[128], s_sh[128];

    if (tid < 128) {
        const float inv = 1.f / 1120.f;   // N*7*10
        float m = g_acc[128 + tid] * inv;
        float v = g_acc[256 + tid] * inv - m * m;
        float sc = bn1_g[tid] * rsqrtf(v + EPSV);
        s_sc[tid] = sc; s_sh[tid] = bn1_b[tid] - m * sc;
    }
    __syncthreads();
    for (int i = tid; i < 128 * 10; i += 256) {
        int ic = i / 10, w = i % 10;
        s_x[ic][w + 1] = tanhf(g_y1[((n * 128 + ic) * 7 + fr) * 10 + w] * s_sc[ic] + s_sh[ic]);
    }
    if (tid < 128) s_x[tid][0] = 0.f;
    __syncthreads();

    const int oc = tid;
    const float4* wr = reinterpret_cast<const float4*>(w2 + oc * 384);
    float acc[5] = {0, 0, 0, 0, 0};

    #pragma unroll 4
    for (int icg = 0; icg < 32; icg++) {   // 4 ic per group, 3 float4 of weights
        float4 wa = wr[icg * 3 + 0];
        float4 wb = wr[icg * 3 + 1];
        float4 wc = wr[icg * 3 + 2];
        float wv[12] = {wa.x, wa.y, wa.z, wa.w, wb.x, wb.y, wb.z, wb.w,
                        wc.x, wc.y, wc.z, wc.w};
        const int ic0 = icg * 4;
        #pragma unroll
        for (int ii = 0; ii < 4; ii++) {
            #pragma unroll
            for (int k = 0; k < 3; k++) {
                float wf = wv[ii * 3 + k];
                #pragma unroll
                for (int m = 0; m < 5; m++)
                    acc[m] += wf * s_x[ic0 + ii][2 * m + k];
            }
        }
    }

    float ps = 0.f, psq = 0.f;
    #pragma unroll
    for (int m = 0; m < 5; m++) {
        g_y2[((n * 256 + oc) * 7 + fr) * 5 + m] = acc[m];
        ps += acc[m]; psq += acc[m] * acc[m];
    }
    atomicAdd(&g_acc[384 + oc], ps);
    atomicAdd(&g_acc[640 + oc], psq);
}

// ---------------------------------------------------------------------------
// K8: bn2 + tanh + mean over width (AvgPool (1,5)). 28672 outputs.
// ---------------------------------------------------------------------------
__global__ void __launch_bounds__(256) k8_final(const float* __restrict__ bn2_g,
                                                const float* __restrict__ bn2_b,
                                                float* __restrict__ out) {
    const int o = blockIdx.x * 256 + threadIdx.x;
    if (o >= NB * OUTC * 7) return;
    const int oc = (o / 7) % OUTC;
    const float inv = 1.f / 560.f;        // N*7*5
    float m = g_acc[384 + oc] * inv;
    float v = g_acc[640 + oc] * inv - m * m;
    float sc = bn2_g[oc] * rsqrtf(v + EPSV);
    float sh = bn2_b[oc] - m * sc;
    const float* y = &g_y2[o * 5];        // (n,oc,fr) contiguous * 5
    float a = 0.f;
    #pragma unroll
    for (int w = 0; w < 5; w++) a += tanhf(y[w] * sc + sh);
    out[o] = a * 0.2f;
}

// ---------------------------------------------------------------------------
extern "C" void kernel_launch(void* const* d_in, const int* in_sizes, int n_in,
                              void* d_out, int out_size) {
    const float* h      = (const float*)d_in[0];
    const float* bn0_g  = (const float*)d_in[1];
    const float* bn0_b  = (const float*)d_in[2];
    const float* up_w   = (const float*)d_in[3];
    const float* up_b   = (const float*)d_in[4];
    const float* up2_w  = (const float*)d_in[5];
    const float* up2_b  = (const float*)d_in[6];
    const float* up3_w  = (const float*)d_in[7];
    const float* up3_b  = (const float*)d_in[8];
    const float* wW     = (const float*)d_in[9];
    const float* wproj  = (const float*)d_in[10];
    const float* wW2    = (const float*)d_in[11];
    const float* wproj2 = (const float*)d_in[12];
    const float* conv1w = (const float*)d_in[13];
    const float* bn1_g  = (const float*)d_in[14];
    const float* bn1_b  = (const float*)d_in[15];
    const float* conv2w = (const float*)d_in[16];
    const float* bn2_g  = (const float*)d_in[17];
    const float* bn2_b  = (const float*)d_in[18];

    k_zero<<<1, 896>>>();
    k1_stats_top5<<<ROWS, 256>>>(h);
    k3_attn<<<NB * CC, 256>>>(bn0_g, bn0_b, up_w, up_b, up2_w, up2_b,
                              up3_w, up3_b, wW, wproj, wW2, wproj2);
    k4_conv1<<<NB * 7, 256>>>(conv1w);
    k6_conv2<<<NB * 7, 256>>>(conv2w, bn1_g, bn1_b);
    k8_final<<<(NB * OUTC * 7 + 255) / 256, 256>>>(bn2_g, bn2_b, (float*)d_out);
}

// round 15
// speedup vs baseline: 1.4081x; 1.0035x over previous
#include <cuda_runtime.h>
#include <cuda_bf16.h>
#include <math.h>

// Shapes (fixed by problem)
#define NB   16
#define CC   64
#define FF   8
#define HWSZ 3136          // 56*56
#define ROWS (NB*CC*FF)    // 8192
#define ITER 128
#define OUTC 256
#define EMB  20
#define EPSV 1e-5f

// Scratch (__device__ globals; no allocation allowed)
// acc layout: [0:64) bn0 sum, [64:128) bn0 sq, [128:256) bn1 sum,
//             [256:384) bn1 sq, [384:640) bn2 sum, [640:896) bn2 sq
__device__ float g_acc[896];
__device__ float g_top5[ROWS * 5];
__device__ float g_si[NB * CC * 7 * 20];     // 143360
__device__ float g_y1[NB * ITER * 7 * 10];   // 143360
__device__ float g_y2[NB * OUTC * 7 * 5];    // 143360

__global__ void k_zero() {
    if (threadIdx.x < 896) g_acc[threadIdx.x] = 0.f;
}

// ---------------------------------------------------------------------------
// K1: one block per (n,c,f) row (8192 blocks). Streams 3136 floats,
// accumulates per-channel sum/sumsq (atomics) and raw top-5 (block tree merge).
// Monotone-BN trick: top5(bn(x)) == bn(top5(x)) since bn scale > 0.
// ---------------------------------------------------------------------------
__global__ void __launch_bounds__(256) k1_stats_top5(const float* __restrict__ h) {
    const int row = blockIdx.x;
    const int c = (row / FF) % CC;
    const float4* p = reinterpret_cast<const float4*>(h + (size_t)row * HWSZ);

    float t0 = -1e30f, t1 = -1e30f, t2 = -1e30f, t3 = -1e30f, t4 = -1e30f;
    float s = 0.f, sq = 0.f;

    for (int i = threadIdx.x; i < HWSZ / 4; i += 256) {
        float4 v4 = p[i];
        #pragma unroll
        for (int j = 0; j < 4; j++) {
            float v = (&v4.x)[j];
            s += v; sq += v * v;
            if (v > t4) {
                if (v > t2) {
                    if (v > t0)      { t4 = t3; t3 = t2; t2 = t1; t1 = t0; t0 = v; }
                    else if (v > t1) { t4 = t3; t3 = t2; t2 = t1; t1 = v; }
                    else             { t4 = t3; t3 = t2; t2 = v; }
                } else {
                    if (v > t3)      { t4 = t3; t3 = v; }
                    else             { t4 = v; }
                }
            }
        }
    }

    // sum/sumsq block reduction -> atomics
    __shared__ float s_red[16];
    #pragma unroll
    for (int o = 16; o; o >>= 1) {
        s  += __shfl_down_sync(0xffffffffu, s,  o);
        sq += __shfl_down_sync(0xffffffffu, sq, o);
    }
    const int lane = threadIdx.x & 31, wid = threadIdx.x >> 5;
    if (lane == 0) { s_red[wid] = s; s_red[8 + wid] = sq; }

    // top-5 block tree merge
    __shared__ float stp[256 * 5];
    float* mine = &stp[threadIdx.x * 5];
    mine[0] = t0; mine[1] = t1; mine[2] = t2; mine[3] = t3; mine[4] = t4;
    __syncthreads();

    if (threadIdx.x == 0) {
        float S = 0.f, Q = 0.f;
        #pragma unroll
        for (int w = 0; w < 8; w++) { S += s_red[w]; Q += s_red[8 + w]; }
        atomicAdd(&g_acc[c], S);
        atomicAdd(&g_acc[64 + c], Q);
    }

    for (int str = 128; str > 0; str >>= 1) {
        if (threadIdx.x < str) {
            float a[5], b[5];
            #pragma unroll
            for (int k = 0; k < 5; k++) { a[k] = mine[k]; b[k] = stp[(threadIdx.x + str) * 5 + k]; }
            int ia = 0, ib = 0;
            #pragma unroll
            for (int k = 0; k < 5; k++) mine[k] = (a[ia] >= b[ib]) ? a[ia++] : b[ib++];
        }
        __syncthreads();
    }
    if (threadIdx.x < 5) g_top5[row * 5 + threadIdx.x] = stp[threadIdx.x];
}

// ---------------------------------------------------------------------------
// K3: one block per (n,c) (1024 blocks). Full attention chain in shared mem.
// ---------------------------------------------------------------------------
__global__ void __launch_bounds__(256) k3_attn(
    const float* __restrict__ bn0_g, const float* __restrict__ bn0_b,
    const float* __restrict__ up_w,  const float* __restrict__ up_b,
    const float* __restrict__ up2_w, const float* __restrict__ up2_b,
    const float* __restrict__ up3_w, const float* __restrict__ up3_b,
    const float* __restrict__ wW,    const float* __restrict__ wproj,
    const float* __restrict__ wW2,   const float* __restrict__ wproj2)
{
    const int b = blockIdx.x;          // n*64 + c
    const int c = b & 63;
    const int tid = threadIdx.x;

    __shared__ float s5[8][5], st[8][25], su[8][25], spa[8][5], ssc[8][25];
    __shared__ float scen[8][2], sc20[7][20], su2[7][20], satt2[8], sbn[2];

    if (tid == 0) {
        const float inv = 1.f / 401408.f;   // N*F*H*W
        float m = g_acc[c] * inv;
        float v = g_acc[64 + c] * inv - m * m;
        float sc = bn0_g[c] * rsqrtf(v + EPSV);
        sbn[0] = sc; sbn[1] = bn0_b[c] - m * sc;
    }
    __syncthreads();

    if (tid < 40) {
        s5[tid / 5][tid % 5] = g_top5[b * 40 + tid] * sbn[0] + sbn[1];
    }
    __syncthreads();

    if (tid < 200) {                    // t = top5 @ up2_w.T + up2_b
        int f = tid / 25, j = tid % 25;
        float a = up2_b[j];
        #pragma unroll
        for (int k = 0; k < 5; k++) a += s5[f][k] * up2_w[j * 5 + k];
        st[f][j] = a;
    }
    __syncthreads();

    if (tid < 200) {                    // u = tanh(t @ wW)
        int f = tid / 25, j = tid % 25;
        float a = 0.f;
        #pragma unroll
        for (int k = 0; k < 25; k++) a += st[f][k] * wW[k * 25 + j];
        su[f][j] = tanhf(a);
    }
    __syncthreads();

    if (tid < 8) {                      // att = softmax(u@wproj); t3; pa = t3*att
        int f = tid;
        float lg[5], t3v[5];
        #pragma unroll
        for (int a2 = 0; a2 < 5; a2++) {
            float l = 0.f, t3 = up3_b[a2];
            #pragma unroll
            for (int k = 0; k < 25; k++) {
                l  += su[f][k] * wproj[k * 5 + a2];
                t3 += st[f][k] * up3_w[a2 * 25 + k];
            }
            lg[a2] = l; t3v[a2] = t3;
        }
        float mx = lg[0];
        #pragma unroll
        for (int a2 = 1; a2 < 5; a2++) mx = fmaxf(mx, lg[a2]);
        float sum = 0.f;
        #pragma unroll
        for (int a2 = 0; a2 < 5; a2++) { lg[a2] = __expf(lg[a2] - mx); sum += lg[a2]; }
        float r = 1.f / sum;
        #pragma unroll
        for (int a2 = 0; a2 < 5; a2++) spa[f][a2] = t3v[a2] * lg[a2] * r;
    }
    __syncthreads();

    if (tid < 200) {                    // scored = pa @ up2_w.T + up2_b
        int f = tid / 25, j = tid % 25;
        float a = up2_b[j];
        #pragma unroll
        for (int k = 0; k < 5; k++) a += spa[f][k] * up2_w[j * 5 + k];
        ssc[f][j] = a;
    }
    __syncthreads();

    if (tid < 16) {                     // cen = scored @ coords
        int f = tid >> 1, d = tid & 1;
        float a = 0.f;
        #pragma unroll
        for (int j = 0; j < 25; j++) {
            float cd = d ? (float)(j % 5) : (float)(j / 5);
            a += ssc[f][j] * cd;
        }
        scen[f][d] = a;
    }
    __syncthreads();

    if (tid < 140) {                    // frame diff, then @ up_w.T + up_b
        int fr = tid / 20, k = tid % 20;
        float d0 = scen[fr + 1][0] - scen[fr][0];
        float d1 = scen[fr + 1][1] - scen[fr][1];
        sc20[fr][k] = d0 * up_w[k * 2] + d1 * up_w[k * 2 + 1] + up_b[k];
    }
    __syncthreads();

    if (tid < 140) {                    // u2 = tanh(wW2 @ cen)
        int fr = tid / 20, k = tid % 20;
        float a = 0.f;
        #pragma unroll
        for (int j = 0; j < 7; j++) a += wW2[fr * 7 + j] * sc20[j][k];
        su2[fr][k] = tanhf(a);
    }
    __syncthreads();

    if (tid < 7) {                      // logits over frames
        float a = 0.f;
        #pragma unroll
        for (int k = 0; k < 20; k++) a += su2[tid][k] * wproj2[k];
        satt2[tid] = a;
    }
    __syncthreads();
    if (tid == 0) {                     // softmax over 7 frames
        float mx = satt2[0];
        #pragma unroll
        for (int j = 1; j < 7; j++) mx = fmaxf(mx, satt2[j]);
        float sum = 0.f;
        #pragma unroll
        for (int j = 0; j < 7; j++) { satt2[j] = __expf(satt2[j] - mx); sum += satt2[j]; }
        float r = 1.f / sum;
        #pragma unroll
        for (int j = 0; j < 7; j++) satt2[j] *= r;
    }
    __syncthreads();

    if (tid < 140) {                    // si = cen * att2
        int fr = tid / 20, k = tid % 20;
        g_si[(b * 7 + fr) * 20 + k] = sc20[fr][k] * satt2[fr];
    }
}

// Accumulate 3-tap conv for one ic. r points at &row[2*ow0]; taps r[2m+k].
#define CONV3ACC(r, w0, w1, w2)                                   \
    {                                                             \
        _Pragma("unroll")                                         \
        for (int m = 0; m < 5; m++)                               \
            acc[m] += (w0) * (r)[2 * m] + (w1) * (r)[2 * m + 1]   \
                    + (w2) * (r)[2 * m + 2];                      \
    }

// ---------------------------------------------------------------------------
// K4: conv1 (128,64,1,3) stride (1,2) pad (0,1) + bn1 stats.
// Block per (n,fr) = 112 blocks. __launch_bounds__(256,1): we never have >1
// block/SM (112 blocks < 148 SMs), so let ptxas keep the 12-float4 weight
// batch register-resident (R13 profile showed regs=32 serialized the LDGs).
// ---------------------------------------------------------------------------
__global__ void __launch_bounds__(256, 1) k4_conv1(const float* __restrict__ w1) {
    const int nb = blockIdx.x, n = nb / 7, fr = nb % 7;
    const int tid = threadIdx.x;
    __shared__ float s_in[64][22];        // zero-padded left column, +pad

    for (int i = tid; i < 64 * 20; i += 256) {
        int ic = i / 20, w = i % 20;
        s_in[ic][w + 1] = g_si[((n * 64 + ic) * 7 + fr) * 20 + w];
    }
    if (tid < 64) s_in[tid][0] = 0.f;
    __syncthreads();

    const int oc = tid & 127, half = tid >> 7;
    const float4* wr = reinterpret_cast<const float4*>(w1 + oc * 192);
    const int ow0 = half * 5;
    float acc[5] = {0, 0, 0, 0, 0};

    #pragma unroll 4
    for (int icg = 0; icg < 16; icg++) {   // 4 ic per group, 3 float4 of weights
        float4 wa = wr[icg * 3 + 0];
        float4 wb = wr[icg * 3 + 1];
        float4 wc = wr[icg * 3 + 2];
        const int ic0 = icg * 4;
        CONV3ACC(&s_in[ic0 + 0][2 * ow0], wa.x, wa.y, wa.z);
        CONV3ACC(&s_in[ic0 + 1][2 * ow0], wa.w, wb.x, wb.y);
        CONV3ACC(&s_in[ic0 + 2][2 * ow0], wb.z, wb.w, wc.x);
        CONV3ACC(&s_in[ic0 + 3][2 * ow0], wc.y, wc.z, wc.w);
    }

    float ps = 0.f, psq = 0.f;
    #pragma unroll
    for (int m = 0; m < 5; m++) {
        g_y1[((n * 128 + oc) * 7 + fr) * 10 + ow0 + m] = acc[m];
        ps += acc[m]; psq += acc[m] * acc[m];
    }
    atomicAdd(&g_acc[128 + oc], ps);
    atomicAdd(&g_acc[256 + oc], psq);
}

// ---------------------------------------------------------------------------
// K6: tanh(bn1(y1)) inline, conv2 (256,128,1,3) stride (1,2) pad (0,1) + bn2
// stats. Block per (n,fr) = 112 blocks, thread per oc. Same register fix.
// ---------------------------------------------------------------------------
__global__ void __launch_bounds__(256, 1) k6_conv2(const float* __restrict__ w2,
                                                   const float* __restrict__ bn1_g,
                                                   const float* __restrict__ bn1_b) {
    const int nb = blockIdx.x, n = nb / 7, fr = nb % 7;
    const int tid = threadIdx.x;
    __shared__ float s_x[128][12];        // zero-padded left column, +pad
    __shared__ float s_sc[128], s_sh[128];

    if (tid < 128) {
        const float inv = 1.f / 1120.f;   // N*7*10
        float m = g_acc[128 + tid] * inv;
        float v = g_acc[256 + tid] * inv - m * m;
        float sc = bn1_g[tid] * rsqrtf(v + EPSV);
        s_sc[tid] = sc; s_sh[tid] = bn1_b[tid] - m * sc;
    }
    __syncthreads();
    for (int i = tid; i < 128 * 10; i += 256) {
        int ic = i / 10, w = i % 10;
        s_x[ic][w + 1] = tanhf(g_y1[((n * 128 + ic) * 7 + fr) * 10 + w] * s_sc[ic] + s_sh[ic]);
    }
    if (tid < 128) s_x[tid][0] = 0.f;
    __syncthreads();

    const int oc = tid;
    const float4* wr = reinterpret_cast<const float4*>(w2 + oc * 384);
    float acc[5] = {0, 0, 0, 0, 0};

    #pragma unroll 4
    for (int icg = 0; icg < 32; icg++) {   // 4 ic per group, 3 float4 of weights
        float4 wa = wr[icg * 3 + 0];
        float4 wb = wr[icg * 3 + 1];
        float4 wc = wr[icg * 3 + 2];
        const int ic0 = icg * 4;
        CONV3ACC(&s_x[ic0 + 0][0], wa.x, wa.y, wa.z);
        CONV3ACC(&s_x[ic0 + 1][0], wa.w, wb.x, wb.y);
        CONV3ACC(&s_x[ic0 + 2][0], wb.z, wb.w, wc.x);
        CONV3ACC(&s_x[ic0 + 3][0], wc.y, wc.z, wc.w);
    }

    float ps = 0.f, psq = 0.f;
    #pragma unroll
    for (int m = 0; m < 5; m++) {
        g_y2[((n * 256 + oc) * 7 + fr) * 5 + m] = acc[m];
        ps += acc[m]; psq += acc[m] * acc[m];
    }
    atomicAdd(&g_acc[384 + oc], ps);
    atomicAdd(&g_acc[640 + oc], psq);
}

// ---------------------------------------------------------------------------
// K8: bn2 + tanh + mean over width (AvgPool (1,5)). 28672 outputs.
// ---------------------------------------------------------------------------
__global__ void __launch_bounds__(256) k8_final(const float* __restrict__ bn2_g,
                                                const float* __restrict__ bn2_b,
                                                float* __restrict__ out) {
    const int o = blockIdx.x * 256 + threadIdx.x;
    if (o >= NB * OUTC * 7) return;
    const int oc = (o / 7) % OUTC;
    const float inv = 1.f / 560.f;        // N*7*5
    float m = g_acc[384 + oc] * inv;
    float v = g_acc[640 + oc] * inv - m * m;
    float sc = bn2_g[oc] * rsqrtf(v + EPSV);
    float sh = bn2_b[oc] - m * sc;
    const float* y = &g_y2[o * 5];        // (n,oc,fr) contiguous * 5
    float a = 0.f;
    #pragma unroll
    for (int w = 0; w < 5; w++) a += tanhf(y[w] * sc + sh);
    out[o] = a * 0.2f;
}

// ---------------------------------------------------------------------------
extern "C" void kernel_launch(void* const* d_in, const int* in_sizes, int n_in,
                              void* d_out, int out_size) {
    const float* h      = (const float*)d_in[0];
    const float* bn0_g  = (const float*)d_in[1];
    const float* bn0_b  = (const float*)d_in[2];
    const float* up_w   = (const float*)d_in[3];
    const float* up_b   = (const float*)d_in[4];
    const float* up2_w  = (const float*)d_in[5];
    const float* up2_b  = (const float*)d_in[6];
    const float* up3_w  = (const float*)d_in[7];
    const float* up3_b  = (const float*)d_in[8];
    const float* wW     = (const float*)d_in[9];
    const float* wproj  = (const float*)d_in[10];
    const float* wW2    = (const float*)d_in[11];
    const float* wproj2 = (const float*)d_in[12];
    const float* conv1w = (const float*)d_in[13];
    const float* bn1_g  = (const float*)d_in[14];
    const float* bn1_b  = (const float*)d_in[15];
    const float* conv2w = (const float*)d_in[16];
    const float* bn2_g  = (const float*)d_in[17];
    const float* bn2_b  = (const float*)d_in[18];

    k_zero<<<1, 896>>>();
    k1_stats_top5<<<ROWS, 256>>>(h);
    k3_attn<<<NB * CC, 256>>>(bn0_g, bn0_b, up_w, up_b, up2_w, up2_b,
                              up3_w, up3_b, wW, wproj, wW2, wproj2);
    k4_conv1<<<NB * 7, 256>>>(conv1w);
    k6_conv2<<<NB * 7, 256>>>(conv2w, bn1_g, bn1_b);
    k8_final<<<(NB * OUTC * 7 + 255) / 256, 256>>>(bn2_g, bn2_b, (float*)d_out);
}